// round 2
// baseline (speedup 1.0000x reference)
#include <cuda_runtime.h>

// Problem constants
#define N_IMG   64
#define C_IN    64
#define H_IN    128
#define W_IN    128
#define KH      3
#define KW      3
#define OH      126
#define OW      126

// Tiling
#define TILE    64            // 64x64 output tile per block
#define SM_W    66            // (TILE + KW - 1)
#define SM_H    66            // (TILE + KH - 1)
#define THREADS 256
#define ROWS_PER_THREAD 16    // each thread: 1 column x 16 output rows
#define KER_ELEMS (C_IN * KH * KW)   // 576

__global__ __launch_bounds__(THREADS, 2)
void imagewise_conv2d_kernel(const float* __restrict__ images,
                             const float* __restrict__ kernels,
                             float* __restrict__ out)
{
    __shared__ float s_img[SM_H * SM_W];    // 66*66*4 = 17424 B
    __shared__ float s_ker[KER_ELEMS];      // 576*4 = 2304 B

    const int tid = threadIdx.x;
    const int n   = blockIdx.z;
    const int ox0 = blockIdx.x * TILE;
    const int oy0 = blockIdx.y * TILE;

    // Stage this sample's full kernel stack once (576 elems, 256 threads -> strided)
    for (int i = tid; i < KER_ELEMS; i += THREADS) {
        s_ker[i] = kernels[n * KER_ELEMS + i];
    }

    const int tx  = tid & 63;        // output column within tile (0..63)
    const int tyg = tid >> 6;        // row group (0..3), covers rows tyg*16..+15
    const int ybase = tyg * ROWS_PER_THREAD;

    float acc[ROWS_PER_THREAD];
#pragma unroll
    for (int i = 0; i < ROWS_PER_THREAD; ++i) acc[i] = 0.0f;

    const float* img_n = images + (size_t)n * C_IN * H_IN * W_IN;

    for (int c = 0; c < C_IN; ++c) {
        __syncthreads();   // previous channel's compute done before overwrite
                           // (also orders s_ker staging before first use)

        // Load 66x66 input tile for channel c (clamped at image edge).
        const float* img_c = img_n + (size_t)c * H_IN * W_IN;
#pragma unroll
        for (int idx = tid; idx < SM_H * SM_W; idx += THREADS) {
            int ly = idx / SM_W;
            int lx = idx - ly * SM_W;
            int gy = oy0 + ly; if (gy > H_IN - 1) gy = H_IN - 1;
            int gx = ox0 + lx; if (gx > W_IN - 1) gx = W_IN - 1;
            s_img[idx] = img_c[gy * W_IN + gx];
        }

        __syncthreads();

        // Broadcast-load this channel's 3x3 weights into registers
        float w0 = s_ker[c * 9 + 0], w1 = s_ker[c * 9 + 1], w2 = s_ker[c * 9 + 2];
        float w3 = s_ker[c * 9 + 3], w4 = s_ker[c * 9 + 4], w5 = s_ker[c * 9 + 5];
        float w6 = s_ker[c * 9 + 6], w7 = s_ker[c * 9 + 7], w8 = s_ker[c * 9 + 8];

        // Each thread: 18 smem rows feed 16 vertical outputs (9 FMAs each).
        const float* col = s_img + ybase * SM_W + tx;
#pragma unroll
        for (int r = 0; r < ROWS_PER_THREAD + KH - 1; ++r) {
            float a0 = col[r * SM_W + 0];
            float a1 = col[r * SM_W + 1];
            float a2 = col[r * SM_W + 2];
            // output row o receives taps from input row o+ky  => o = r - ky
            if (r - 0 >= 0 && r - 0 < ROWS_PER_THREAD) {
                int o = r;
                acc[o] = fmaf(a0, w0, fmaf(a1, w1, fmaf(a2, w2, acc[o])));
            }
            if (r - 1 >= 0 && r - 1 < ROWS_PER_THREAD) {
                int o = r - 1;
                acc[o] = fmaf(a0, w3, fmaf(a1, w4, fmaf(a2, w5, acc[o])));
            }
            if (r - 2 >= 0 && r - 2 < ROWS_PER_THREAD) {
                int o = r - 2;
                acc[o] = fmaf(a0, w6, fmaf(a1, w7, fmaf(a2, w8, acc[o])));
            }
        }
    }

    // Store valid outputs
    const int gx = ox0 + tx;
    if (gx < OW) {
        float* out_n = out + (size_t)n * OH * OW;
#pragma unroll
        for (int o = 0; o < ROWS_PER_THREAD; ++o) {
            int gy = oy0 + ybase + o;
            if (gy < OH) {
                out_n[gy * OW + gx] = acc[o];
            }
        }
    }
}

extern "C" void kernel_launch(void* const* d_in, const int* in_sizes, int n_in,
                              void* d_out, int out_size)
{
    const float* images  = (const float*)d_in[0];
    const float* kernels = (const float*)d_in[1];
    float* out = (float*)d_out;

    dim3 grid((OW + TILE - 1) / TILE, (OH + TILE - 1) / TILE, N_IMG); // 2 x 2 x 64
    imagewise_conv2d_kernel<<<grid, THREADS>>>(images, kernels, out);
}

// round 5
// speedup vs baseline: 1.3970x; 1.3970x over previous
#include <cuda_runtime.h>
#include <cstdint>

// Problem constants
#define N_IMG   64
#define C_IN    64
#define H_IN    128
#define W_IN    128
#define KH      3
#define KW      3
#define OH      126
#define OW      126

// Tiling
#define TILE    64            // 64x64 output tile per block
#define SM_W    68            // padded tile width (17 float4 chunks, 16B-aligned rows)
#define SM_H    66            // TILE + KH - 1
#define THREADS 256
#define KER_ELEMS (C_IN * KH * KW)   // 576

#define CHUNKS_PER_ROW 17            // 17 * 4 = 68 cols
#define TOTAL_CHUNKS   (SM_H * CHUNKS_PER_ROW)   // 1122
#define CHUNK_ITERS    ((TOTAL_CHUNKS + THREADS - 1) / THREADS)  // 5

__device__ __forceinline__ uint32_t smem_u32(const void* p) {
    uint32_t a;
    asm("{ .reg .u64 t; cvta.to.shared.u64 t, %1; cvt.u32.u64 %0, t; }" : "=r"(a) : "l"(p));
    return a;
}

__device__ __forceinline__ void cp_async16(uint32_t smem_addr, const void* gptr) {
    asm volatile("cp.async.cg.shared.global [%0], [%1], 16;\n" :: "r"(smem_addr), "l"(gptr));
}
__device__ __forceinline__ void cp_commit() {
    asm volatile("cp.async.commit_group;\n" ::: "memory");
}
__device__ __forceinline__ void cp_wait1() {
    asm volatile("cp.async.wait_group 1;\n" ::: "memory");
}

__global__ __launch_bounds__(THREADS, 2)
void imagewise_conv2d_kernel(const float* __restrict__ images,
                             const float* __restrict__ kernels,
                             float* __restrict__ out)
{
    __shared__ float s_img[2][SM_H * SM_W];   // 2 * 66*68*4 = 35904 B
    __shared__ float s_ker[KER_ELEMS];        //  576*4 =  2304 B

    const int tid = threadIdx.x;
    const int n   = blockIdx.z;
    const int ox0 = blockIdx.x * TILE;
    const int oy0 = blockIdx.y * TILE;

    // Stage this sample's full kernel stack once
    for (int i = tid; i < KER_ELEMS; i += THREADS) {
        s_ker[i] = kernels[n * KER_ELEMS + i];
    }

    const float* img_n = images + (size_t)n * C_IN * H_IN * W_IN;

    // ---- Precompute per-thread cp.async chunk addresses (channel-invariant) ----
    // Chunk j covers smem row = j/17, cols 4k..4k+3 (k = j%17).
    // Global: gy = clamp(oy0+row, 127), gx = min(ox0+4k, 124). Clamped chunks fill
    // smem cells that only feed never-stored outputs.
    int      g_off[CHUNK_ITERS];     // float offset within one channel image
    uint32_t s_off[CHUNK_ITERS];     // byte offset within one smem buffer
    bool     valid[CHUNK_ITERS];
#pragma unroll
    for (int it = 0; it < CHUNK_ITERS; ++it) {
        int j = tid + it * THREADS;
        valid[it] = (j < TOTAL_CHUNKS);
        if (!valid[it]) j = TOTAL_CHUNKS - 1;
        int row = j / CHUNKS_PER_ROW;
        int k   = j - row * CHUNKS_PER_ROW;
        int gy  = oy0 + row; if (gy > H_IN - 1) gy = H_IN - 1;
        int gx  = ox0 + 4 * k; if (gx > W_IN - 4) gx = W_IN - 4;
        g_off[it] = gy * W_IN + gx;
        s_off[it] = (uint32_t)((row * SM_W + 4 * k) * sizeof(float));
    }
    const uint32_t s_base0 = smem_u32(&s_img[0][0]);
    const uint32_t s_base1 = smem_u32(&s_img[1][0]);

    // ---- Compute mapping: 4 cols x 4 rows per thread ----
    const int tx   = tid & 15;        // 0..15 -> cols 4tx..4tx+3
    const int tyg  = tid >> 4;        // 0..15 -> rows 4tyg..4tyg+3
    const int col0 = 4 * tx;
    const int row0 = 4 * tyg;

    float acc[4][4];
#pragma unroll
    for (int o = 0; o < 4; ++o)
#pragma unroll
        for (int cc = 0; cc < 4; ++cc) acc[o][cc] = 0.0f;

    // ---- Prologue: prefetch channel 0 into buf 0 ----
    {
        const float* img_c = img_n;   // c = 0
#pragma unroll
        for (int it = 0; it < CHUNK_ITERS; ++it)
            if (valid[it]) cp_async16(s_base0 + s_off[it], img_c + g_off[it]);
        cp_commit();
    }

    // ---- Main loop over channels, double-buffered ----
    for (int c = 0; c < C_IN; ++c) {
        __syncthreads();   // all warps done reading buf[(c+1)&1] (from compute c-1)

        // Prefetch next channel (wraps to 0 at the end; harmless redundant load)
        {
            int cn = (c + 1) & (C_IN - 1);
            const float* img_c = img_n + (size_t)cn * H_IN * W_IN;
            uint32_t sb = ((c + 1) & 1) ? s_base1 : s_base0;
#pragma unroll
            for (int it = 0; it < CHUNK_ITERS; ++it)
                if (valid[it]) cp_async16(sb + s_off[it], img_c + g_off[it]);
            cp_commit();
        }

        cp_wait1();        // channel c's group complete
        __syncthreads();   // make async-filled smem visible to all warps

        const float* buf = s_img[c & 1];

        // Channel c's 3x3 weights (broadcast LDS)
        const float w0 = s_ker[c * 9 + 0], w1 = s_ker[c * 9 + 1], w2 = s_ker[c * 9 + 2];
        const float w3 = s_ker[c * 9 + 3], w4 = s_ker[c * 9 + 4], w5 = s_ker[c * 9 + 5];
        const float w6 = s_ker[c * 9 + 6], w7 = s_ker[c * 9 + 7], w8 = s_ker[c * 9 + 8];

        const float* colp = buf + row0 * SM_W + col0;
#pragma unroll
        for (int r = 0; r < 4 + KH - 1; ++r) {   // 6 input rows
            float4 f4 = *(const float4*)(colp + r * SM_W);
            float2 f2 = *(const float2*)(colp + r * SM_W + 4);
            float x[6] = {f4.x, f4.y, f4.z, f4.w, f2.x, f2.y};

            // output row o uses input row r when ky = r - o in [0,3)
#pragma unroll
            for (int o = 0; o < 4; ++o) {
                int ky = r - o;
                if (ky >= 0 && ky < KH) {
                    float wa = (ky == 0) ? w0 : (ky == 1) ? w3 : w6;
                    float wb = (ky == 0) ? w1 : (ky == 1) ? w4 : w7;
                    float wc = (ky == 0) ? w2 : (ky == 1) ? w5 : w8;
#pragma unroll
                    for (int cc = 0; cc < 4; ++cc) {
                        acc[o][cc] = fmaf(x[cc + 0], wa,
                                     fmaf(x[cc + 1], wb,
                                     fmaf(x[cc + 2], wc, acc[o][cc])));
                    }
                }
            }
        }
    }

    // ---- Store valid outputs ----
    float* out_n = out + (size_t)n * OH * OW;
#pragma unroll
    for (int o = 0; o < 4; ++o) {
        int gy = oy0 + row0 + o;
        if (gy < OH) {
#pragma unroll
            for (int cc = 0; cc < 4; ++cc) {
                int gx = ox0 + col0 + cc;
                if (gx < OW) {
                    out_n[gy * OW + gx] = acc[o][cc];
                }
            }
        }
    }
}

extern "C" void kernel_launch(void* const* d_in, const int* in_sizes, int n_in,
                              void* d_out, int out_size)
{
    const float* images  = (const float*)d_in[0];
    const float* kernels = (const float*)d_in[1];
    float* out = (float*)d_out;

    dim3 grid((OW + TILE - 1) / TILE, (OH + TILE - 1) / TILE, N_IMG); // 2 x 2 x 64
    imagewise_conv2d_kernel<<<grid, THREADS>>>(images, kernels, out);
}